// round 1
// baseline (speedup 1.0000x reference)
#include <cuda_runtime.h>
#include <cstdint>

#define HDIM  128
#define WDIM  128
#define N_PIX 16384          // H*W
#define BATCH 64

// Scratch (allocation-free: __device__ globals)
__device__ unsigned long long g_spikemask[N_PIX];          // bit b set if S0[b, n] != 0
__device__ float              g_global[BATCH * (size_t)N_PIX]; // g[b][m], 4 MB

// ---------------------------------------------------------------------------
// Kernel 1: build per-pixel spike bitmask + zero g
// ---------------------------------------------------------------------------
__global__ void __launch_bounds__(256) prep_kernel(const float* __restrict__ S0) {
    int tid = blockIdx.x * blockDim.x + threadIdx.x;
    int stride = gridDim.x * blockDim.x;

    if (tid < N_PIX) {
        unsigned long long m = 0ULL;
        #pragma unroll
        for (int b = 0; b < BATCH; b++) {
            float s = S0[(size_t)b * N_PIX + tid];   // coalesced across threads
            if (s != 0.0f) m |= (1ULL << b);
        }
        g_spikemask[tid] = m;
    }

    // zero g with vector stores
    float4* g4 = reinterpret_cast<float4*>(g_global);
    const int total4 = BATCH * N_PIX / 4;
    for (int i = tid; i < total4; i += stride)
        g4[i] = make_float4(0.f, 0.f, 0.f, 0.f);
}

// ---------------------------------------------------------------------------
// Kernel 2: stream the 1 GiB matrix, scatter nonzeros into g
// g[b][m] += M[n][m] for every batch b with S0[b][n] != 0
// ---------------------------------------------------------------------------
__device__ __forceinline__ void handle_nz(size_t idx, float val) {
    int n = (int)(idx >> 14);        // row
    int m = (int)(idx & 16383);      // col
    unsigned long long mask = g_spikemask[n];
    while (mask) {
        int b = __ffsll((long long)mask) - 1;
        atomicAdd(&g_global[(size_t)b * N_PIX + m], val);
        mask &= mask - 1;
    }
}

__device__ __forceinline__ void check4(const float4& v, size_t base) {
    unsigned nz = __float_as_uint(v.x) | __float_as_uint(v.y) |
                  __float_as_uint(v.z) | __float_as_uint(v.w);
    if (nz != 0u) {
        if (v.x != 0.0f) handle_nz(base + 0, v.x);
        if (v.y != 0.0f) handle_nz(base + 1, v.y);
        if (v.z != 0.0f) handle_nz(base + 2, v.z);
        if (v.w != 0.0f) handle_nz(base + 3, v.w);
    }
}

__global__ void __launch_bounds__(256) scan_kernel(const float4* __restrict__ M4) {
    const size_t total  = (size_t)N_PIX * N_PIX / 4;      // 67,108,864 float4
    const size_t stride = (size_t)gridDim.x * blockDim.x; // 524,288
    size_t i = (size_t)blockIdx.x * blockDim.x + threadIdx.x;

    // 4 independent 128B loads in flight per thread (MLP to cover DRAM latency)
    for (; i + 3 * stride < total; i += 4 * stride) {
        float4 a = __ldcs(M4 + i);
        float4 b = __ldcs(M4 + i + stride);
        float4 c = __ldcs(M4 + i + 2 * stride);
        float4 d = __ldcs(M4 + i + 3 * stride);
        check4(a, (i) * 4);
        check4(b, (i + stride) * 4);
        check4(c, (i + 2 * stride) * 4);
        check4(d, (i + 3 * stride) * 4);
    }
    for (; i < total; i += stride) {
        float4 a = __ldcs(M4 + i);
        check4(a, i * 4);
    }
}

// ---------------------------------------------------------------------------
// Kernel 3: box convs (separable circular window sums) + fused update.
// One block per batch. Dynamic smem: rs7[16384] + rs5[16384] = 128 KB.
// ---------------------------------------------------------------------------
__global__ void fused_kernel(
    const float* __restrict__ V0, const float* __restrict__ S0,
    const float* __restrict__ U,
    const float* __restrict__ exc_w_p, const float* __restrict__ inh_w_p,
    const float* __restrict__ p_decay, const float* __restrict__ p_thr,
    const float* __restrict__ p_reset, const float* __restrict__ p_split,
    const float* __restrict__ p_excl,  const float* __restrict__ p_excg,
    const float* __restrict__ p_inhl,  const float* __restrict__ p_inhg,
    const float* __restrict__ p_drop,  const float* __restrict__ p_lower,
    float* __restrict__ out)
{
    extern __shared__ float sm[];
    float* rs7 = sm;            // horizontal 7-window sums
    float* rs5 = sm + N_PIX;    // horizontal 5-window sums

    const int b = blockIdx.x;
    const int t = threadIdx.x;
    const float* S = S0 + (size_t)b * N_PIX;

    // Phase A: horizontal circular window sums (reads hit L1, image = 64 KB)
    for (int i = t; i < N_PIX; i += blockDim.x) {
        int h = i >> 7, w = i & 127;
        const float* row = S + (h << 7);
        float s7 = 0.f, s5 = 0.f;
        #pragma unroll
        for (int d = -3; d <= 3; d++) {
            float v = row[(w + d) & 127];
            s7 += v;
            if (d >= -2 && d <= 2) s5 += v;
        }
        rs7[i] = s7;
        rs5[i] = s5;
    }
    __syncthreads();

    const float decay = *p_decay, thr = *p_thr, rst = *p_reset, split = *p_split;
    const float excl = *p_excl, excg = *p_excg, inhl = *p_inhl, inhg = *p_inhg;
    const float drop = *p_drop, lower = *p_lower;
    const float w7 = *exc_w_p, w5 = *inh_w_p;       // 1/49, 1/25 (exact f32 from ref)
    const float oms = 1.0f - split;

    float* outV = out;
    float* outS = out + (size_t)BATCH * N_PIX;
    float* outY = out + (size_t)2 * BATCH * N_PIX;

    for (int i = t; i < N_PIX; i += blockDim.x) {
        int h = i >> 7, w = i & 127;

        // Phase B: vertical circular window sums (smem, conflict-free: bank = w%32)
        float c7 = 0.f, c5 = 0.f;
        #pragma unroll
        for (int d = -3; d <= 3; d++) {
            int hh = (h + d) & 127;
            c7 += rs7[(hh << 7) + w];
            if (d >= -2 && d <= 2) c5 += rs5[(hh << 7) + w];
        }

        size_t gi = (size_t)b * N_PIX + i;
        float v0 = V0[gi], u = U[gi], gg = g_global[gi];

        // V = decay*V0 + input_split*U   (non-fused, matches XLA mul+add)
        float V = __fadd_rn(__fmul_rn(decay, v0), __fmul_rn(split, u));
        bool active = V > lower;

        // lateral = excl*conv7 + inhl*conv5 + excg*g + inhg*g
        float conv7 = __fmul_rn(c7, w7);
        float conv5 = __fmul_rn(c5, w5);
        float lat = __fadd_rn(__fmul_rn(excl, conv7), __fmul_rn(inhl, conv5));
        lat = __fadd_rn(lat, __fmul_rn(excg, gg));
        lat = __fadd_rn(lat, __fmul_rn(inhg, gg));

        if (active)
            V = __fadd_rn(__fadd_rn(V, __fmul_rn(oms, u)), lat);
        V = fminf(fmaxf(V, -2.0f), 2.0f);

        float spike = (V > thr) ? 1.0f : 0.0f;

        // deterministic dropout mask: frac(h + 0.7*w) > drop  (non-fused fp32)
        float a = __fadd_rn((float)h, __fmul_rn(0.7f, (float)w));
        float frac = __fsub_rn(a, floorf(a));
        float mask = (frac > drop) ? 1.0f : 0.0f;
        float sp = __fmul_rn(spike, mask);

        if (sp > 0.0f) V = rst;

        float y = fminf(fmaxf(__fmul_rn(__fadd_rn(V, 1.0f), 0.5f), 0.0f), 1.0f);
        y = __fadd_rn(y, __fmul_rn(0.5f, sp));
        y = fminf(fmaxf(y, 0.0f), 1.0f);

        outV[gi] = V;
        outS[gi] = sp;
        outY[gi] = y;
    }
}

// ---------------------------------------------------------------------------
extern "C" void kernel_launch(void* const* d_in, const int* in_sizes, int n_in,
                              void* d_out, int out_size) {
    const float* V0    = (const float*)d_in[0];
    const float* S0    = (const float*)d_in[1];
    const float* U     = (const float*)d_in[2];
    const float* exc_w = (const float*)d_in[3];
    const float* inh_w = (const float*)d_in[4];
    const float* M     = (const float*)d_in[5];
    const float* decay = (const float*)d_in[6];
    const float* thr   = (const float*)d_in[7];
    const float* reset = (const float*)d_in[8];
    const float* split = (const float*)d_in[9];
    const float* excl  = (const float*)d_in[10];
    const float* excg  = (const float*)d_in[11];
    const float* inhl  = (const float*)d_in[12];
    const float* inhg  = (const float*)d_in[13];
    const float* drop  = (const float*)d_in[14];
    const float* lower = (const float*)d_in[15];
    float* out = (float*)d_out;

    prep_kernel<<<320, 256>>>(S0);
    scan_kernel<<<2048, 256>>>((const float4*)M);

    int smem = 2 * N_PIX * (int)sizeof(float);   // 128 KB
    cudaFuncSetAttribute(fused_kernel, cudaFuncAttributeMaxDynamicSharedMemorySize, smem);
    fused_kernel<<<BATCH, 512, smem>>>(V0, S0, U, exc_w, inh_w,
                                       decay, thr, reset, split,
                                       excl, excg, inhl, inhg, drop, lower,
                                       out);
}

// round 2
// speedup vs baseline: 1.0102x; 1.0102x over previous
#include <cuda_runtime.h>
#include <cstdint>

#define HDIM  128
#define WDIM  128
#define N_PIX 16384          // H*W
#define BATCH 64

#define NSM        148
#define SCAN_GRID  (NSM * 8)    // exactly one full wave at 256 thr/block

// Scratch (allocation-free: __device__ globals)
__device__ unsigned long long g_spikemask[N_PIX];               // bit b set if S0[b, n] != 0
__device__ float              g_global[BATCH * (size_t)N_PIX];  // g[b][m], 4 MB

// ---------------------------------------------------------------------------
// Kernel 1: build per-pixel spike bitmask + zero g (one full wave)
// ---------------------------------------------------------------------------
__global__ void __launch_bounds__(256) prep_kernel(const float* __restrict__ S0) {
    int tid = blockIdx.x * blockDim.x + threadIdx.x;
    int stride = gridDim.x * blockDim.x;

    if (tid < N_PIX) {
        unsigned long long m = 0ULL;
        #pragma unroll
        for (int b = 0; b < BATCH; b++) {
            float s = S0[(size_t)b * N_PIX + tid];   // coalesced across threads
            if (s != 0.0f) m |= (1ULL << b);
        }
        g_spikemask[tid] = m;
    }

    // zero g with vector stores
    float4* g4 = reinterpret_cast<float4*>(g_global);
    const int total4 = BATCH * N_PIX / 4;
    for (int i = tid; i < total4; i += stride)
        g4[i] = make_float4(0.f, 0.f, 0.f, 0.f);
}

// ---------------------------------------------------------------------------
// Kernel 2: stream the 1 GiB matrix, scatter nonzeros into g
// g[b][m] += M[n][m] for every batch b with S0[b][n] != 0
// ---------------------------------------------------------------------------
__device__ __forceinline__ void handle_nz(size_t idx, float val) {
    int n = (int)(idx >> 14);        // row
    int m = (int)(idx & 16383);      // col
    unsigned long long mask = g_spikemask[n];
    while (mask) {
        int b = __ffsll((long long)mask) - 1;
        atomicAdd(&g_global[(size_t)b * N_PIX + m], val);
        mask &= mask - 1;
    }
}

__device__ __forceinline__ void check4(const float4& v, size_t base) {
    unsigned nz = __float_as_uint(v.x) | __float_as_uint(v.y) |
                  __float_as_uint(v.z) | __float_as_uint(v.w);
    if (nz != 0u) {
        if (v.x != 0.0f) handle_nz(base + 0, v.x);
        if (v.y != 0.0f) handle_nz(base + 1, v.y);
        if (v.z != 0.0f) handle_nz(base + 2, v.z);
        if (v.w != 0.0f) handle_nz(base + 3, v.w);
    }
}

__global__ void __launch_bounds__(256) scan_kernel(const float4* __restrict__ M4) {
    const size_t total  = (size_t)N_PIX * N_PIX / 4;      // 67,108,864 float4
    const size_t stride = (size_t)gridDim.x * blockDim.x; // 303,104 (one wave)
    size_t i = (size_t)blockIdx.x * blockDim.x + threadIdx.x;

    // 4 independent 128B loads in flight per thread (MLP to cover DRAM latency)
    for (; i + 3 * stride < total; i += 4 * stride) {
        float4 a = __ldcs(M4 + i);
        float4 b = __ldcs(M4 + i + stride);
        float4 c = __ldcs(M4 + i + 2 * stride);
        float4 d = __ldcs(M4 + i + 3 * stride);
        check4(a, (i) * 4);
        check4(b, (i + stride) * 4);
        check4(c, (i + 2 * stride) * 4);
        check4(d, (i + 3 * stride) * 4);
    }
    for (; i < total; i += stride) {
        float4 a = __ldcs(M4 + i);
        check4(a, i * 4);
    }
}

// ---------------------------------------------------------------------------
// Kernel 3: box convs (separable circular window sums) + fused update.
// Two blocks per batch (64 image rows each + 3-row halo). Smem: 70 rows
// of rs7 + rs5 = 70*128*2*4 = 71,680 B -> up to 2 blocks/SM, 128 blocks total.
// ---------------------------------------------------------------------------
#define ROWS_PER_BLK 64
#define HALO 3
#define SROWS (ROWS_PER_BLK + 2 * HALO)   // 70

__global__ void fused_kernel(
    const float* __restrict__ V0, const float* __restrict__ S0,
    const float* __restrict__ U,
    const float* __restrict__ exc_w_p, const float* __restrict__ inh_w_p,
    const float* __restrict__ p_decay, const float* __restrict__ p_thr,
    const float* __restrict__ p_reset, const float* __restrict__ p_split,
    const float* __restrict__ p_excl,  const float* __restrict__ p_excg,
    const float* __restrict__ p_inhl,  const float* __restrict__ p_inhg,
    const float* __restrict__ p_drop,  const float* __restrict__ p_lower,
    float* __restrict__ out)
{
    extern __shared__ float sm[];
    float* rs7 = sm;                  // horizontal 7-window sums, SROWS x 128
    float* rs5 = sm + SROWS * WDIM;   // horizontal 5-window sums

    const int b  = blockIdx.x >> 1;
    const int r0 = (blockIdx.x & 1) * ROWS_PER_BLK;   // first output row
    const int t  = threadIdx.x;
    const float* S = S0 + (size_t)b * N_PIX;

    // Phase A: horizontal circular window sums for rows r0-3 .. r0+66 (wrapped)
    for (int i = t; i < SROWS * WDIM; i += blockDim.x) {
        int lr = i >> 7, w = i & 127;
        int h = (r0 - HALO + lr) & (HDIM - 1);
        const float* row = S + (h << 7);
        float s7 = 0.f, s5 = 0.f;
        #pragma unroll
        for (int d = -3; d <= 3; d++) {
            float v = row[(w + d) & 127];
            s7 += v;
            if (d >= -2 && d <= 2) s5 += v;
        }
        rs7[i] = s7;
        rs5[i] = s5;
    }
    __syncthreads();

    const float decay = *p_decay, thr = *p_thr, rst = *p_reset, split = *p_split;
    const float excl = *p_excl, excg = *p_excg, inhl = *p_inhl, inhg = *p_inhg;
    const float drop = *p_drop, lower = *p_lower;
    const float w7 = *exc_w_p, w5 = *inh_w_p;       // 1/49, 1/25 (exact f32 from ref)
    const float oms = 1.0f - split;

    float* outV = out;
    float* outS = out + (size_t)BATCH * N_PIX;
    float* outY = out + (size_t)2 * BATCH * N_PIX;

    for (int i = t; i < ROWS_PER_BLK * WDIM; i += blockDim.x) {
        int lr = i >> 7, w = i & 127;
        int h = r0 + lr;

        // Phase B: vertical circular window sums from smem (conflict-free)
        float c7 = 0.f, c5 = 0.f;
        #pragma unroll
        for (int d = -3; d <= 3; d++) {
            int sr = lr + HALO + d;                   // 0..SROWS-1
            c7 += rs7[(sr << 7) + w];
            if (d >= -2 && d <= 2) c5 += rs5[(sr << 7) + w];
        }

        size_t gi = (size_t)b * N_PIX + (h << 7) + w;
        float v0 = V0[gi], u = U[gi], gg = g_global[gi];

        // V = decay*V0 + input_split*U   (non-fused, matches XLA mul+add)
        float V = __fadd_rn(__fmul_rn(decay, v0), __fmul_rn(split, u));
        bool active = V > lower;

        // lateral = excl*conv7 + inhl*conv5 + excg*g + inhg*g
        float conv7 = __fmul_rn(c7, w7);
        float conv5 = __fmul_rn(c5, w5);
        float lat = __fadd_rn(__fmul_rn(excl, conv7), __fmul_rn(inhl, conv5));
        lat = __fadd_rn(lat, __fmul_rn(excg, gg));
        lat = __fadd_rn(lat, __fmul_rn(inhg, gg));

        if (active)
            V = __fadd_rn(__fadd_rn(V, __fmul_rn(oms, u)), lat);
        V = fminf(fmaxf(V, -2.0f), 2.0f);

        float spike = (V > thr) ? 1.0f : 0.0f;

        // deterministic dropout mask: frac(h + 0.7*w) > drop  (non-fused fp32)
        float a = __fadd_rn((float)h, __fmul_rn(0.7f, (float)w));
        float frac = __fsub_rn(a, floorf(a));
        float mask = (frac > drop) ? 1.0f : 0.0f;
        float sp = __fmul_rn(spike, mask);

        if (sp > 0.0f) V = rst;

        float y = fminf(fmaxf(__fmul_rn(__fadd_rn(V, 1.0f), 0.5f), 0.0f), 1.0f);
        y = __fadd_rn(y, __fmul_rn(0.5f, sp));
        y = fminf(fmaxf(y, 0.0f), 1.0f);

        outV[gi] = V;
        outS[gi] = sp;
        outY[gi] = y;
    }
}

// ---------------------------------------------------------------------------
extern "C" void kernel_launch(void* const* d_in, const int* in_sizes, int n_in,
                              void* d_out, int out_size) {
    const float* V0    = (const float*)d_in[0];
    const float* S0    = (const float*)d_in[1];
    const float* U     = (const float*)d_in[2];
    const float* exc_w = (const float*)d_in[3];
    const float* inh_w = (const float*)d_in[4];
    const float* M     = (const float*)d_in[5];
    const float* decay = (const float*)d_in[6];
    const float* thr   = (const float*)d_in[7];
    const float* reset = (const float*)d_in[8];
    const float* split = (const float*)d_in[9];
    const float* excl  = (const float*)d_in[10];
    const float* excg  = (const float*)d_in[11];
    const float* inhl  = (const float*)d_in[12];
    const float* inhg  = (const float*)d_in[13];
    const float* drop  = (const float*)d_in[14];
    const float* lower = (const float*)d_in[15];
    float* out = (float*)d_out;

    prep_kernel<<<SCAN_GRID, 256>>>(S0);
    scan_kernel<<<SCAN_GRID, 256>>>((const float4*)M);

    int smem = 2 * SROWS * WDIM * (int)sizeof(float);   // 71,680 B
    cudaFuncSetAttribute(fused_kernel, cudaFuncAttributeMaxDynamicSharedMemorySize, smem);
    fused_kernel<<<BATCH * 2, 512, smem>>>(V0, S0, U, exc_w, inh_w,
                                           decay, thr, reset, split,
                                           excl, excg, inhl, inhg, drop, lower,
                                           out);
}